// round 9
// baseline (speedup 1.0000x reference)
#include <cuda_runtime.h>

// e3LayerNorm over irreps 128x0e+64x1o+32x2e, graph-segmented (batch sorted).
// out[i,c] = a[g,c]*x[i,c] + b[g,c]; a/b fold mean-subtract, inv-std (scalar
// cols only), weight, bias.
//
// Single-pass persistent kernel: x is read from DRAM exactly ONCE. 16 phases
// of 4 graphs; each of 148 CTAs (1/SM, all resident) stages its row slice in
// SMEM while accumulating stats, crosses a grid barrier, then normalizes from
// SMEM. Total HBM/L2 traffic = 1 read + 1 write (768 MB) -- the floor; prior
// rounds were capped by the ~6 TB/s LTS throughput at 1152 MB of L2 traffic.

#define NTOT    480
#define NC4     120
#define NPAD    121          // SMEM row stride in float4 (bank-conflict pad)
#define NSCAL   128
#define NB      64
#define GG      4            // graphs per phase
#define NPHASES (NB / GG)
#define GRID    148          // 1 CTA/SM -> all resident -> safe grid barrier
#define THREADS 960          // 120 float4 cols x 8 row lanes
#define SROWS   108          // SMEM tile rows (expected slice ~85)
#define EPSV    1e-5f

#define SMEM_BYTES (SROWS * NPAD * 16 + (NTOT + NSCAL + 8) * 4)

__device__ int      g_start[NB + 1];
__device__ float    g_sum[NB][NTOT];
__device__ float    g_sumsq[NB][NSCAL];
__device__ unsigned g_bar;

__global__ void prep_kernel() {
    int i = blockIdx.x * blockDim.x + threadIdx.x;
    if (i < NB * NTOT)  ((float*)g_sum)[i]   = 0.f;
    if (i < NB * NSCAL) ((float*)g_sumsq)[i] = 0.f;
    if (i == 0) g_bar = 0u;
}

// g_start[g] = lower_bound(batch, g). Detects int64 vs int32 batch by probing
// an odd int32 word near the end (int64 high word == 0; int32 value ~63).
__global__ void bounds_kernel(const void* __restrict__ batch_raw, int N) {
    int t = threadIdx.x;
    if (t > NB) return;
    const int* b32 = (const int*)batch_raw;
    const long long* b64 = (const long long*)batch_raw;
    int probe = (N & 1) ? (N - 2) : (N - 1);
    bool is64 = (b32[probe] < 32);
    int lo = 0, hi = N;
    while (lo < hi) {
        int mid = (lo + hi) >> 1;
        long long v = is64 ? b64[mid] : (long long)b32[mid];
        if (v < (long long)t) lo = mid + 1; else hi = mid;
    }
    g_start[t] = lo;
}

__device__ __forceinline__ void acc4(float4& a, float4& q, const float4 v, bool sc) {
    a.x += v.x; a.y += v.y; a.z += v.z; a.w += v.w;
    if (sc) {
        q.x = fmaf(v.x, v.x, q.x); q.y = fmaf(v.y, v.y, q.y);
        q.z = fmaf(v.z, v.z, q.z); q.w = fmaf(v.w, v.w, q.w);
    }
}

__device__ __forceinline__ float4 fma4(const float4 v, const float4 a, const float4 b) {
    float4 o;
    o.x = fmaf(v.x, a.x, b.x); o.y = fmaf(v.y, a.y, b.y);
    o.z = fmaf(v.z, a.z, b.z); o.w = fmaf(v.w, a.w, b.w);
    return o;
}

__global__ __launch_bounds__(THREADS) void persist_kernel(
    const float4* __restrict__ x4,
    const float*  __restrict__ weight,
    const float*  __restrict__ bias,
    float4*       __restrict__ o4)
{
    extern __shared__ float smem[];
    float4* tile  = (float4*)smem;                       // [SROWS][NPAD]
    float*  s_sum = smem + SROWS * NPAD * 4;             // [NTOT]
    float*  s_sq  = s_sum + NTOT;                        // [NSCAL]
    float*  s_nrm = s_sq + NSCAL;                        // [1]

    int t  = threadIdx.x;
    int lc = t % NC4;            // float4 column
    int lr = t / NC4;            // row lane 0..7
    int bid = blockIdx.x;
    bool sc = (lc < 32);         // scalar (0e) float4 columns

    // Per-thread affine constants (column -> weight channel).
    float w4[4], bi4[4];
    #pragma unroll
    for (int k = 0; k < 4; ++k) {
        int c = lc * 4 + k;
        int ch = (c < NSCAL) ? c : (c < 320 ? 128 + (c - 128) / 3
                                            : 192 + (c - 320) / 5);
        w4[k]  = weight[ch];
        bi4[k] = (c < NSCAL) ? bias[c] : 0.f;
    }

    for (int ph = 0; ph < NPHASES; ++ph) {
        int G0 = ph * GG;
        int s0 = g_start[G0], s1 = g_start[G0 + GG];
        long long len = (long long)(s1 - s0);
        int r0 = s0 + (int)(len * bid / GRID);
        int r1 = s0 + (int)(len * (bid + 1) / GRID);

        // ---------- stage tile + accumulate stats ----------
        for (int g = G0; g < G0 + GG; ++g) {
            int ga = max(r0, g_start[g]);
            int gb = min(r1, g_start[g + 1]);
            if (ga >= gb) continue;                   // uniform per CTA

            __syncthreads();                          // prior flush reads done
            if (t < NTOT)  s_sum[t] = 0.f;
            if (t < NSCAL) s_sq[t]  = 0.f;
            __syncthreads();

            float4 a0 = {0,0,0,0}, a1 = {0,0,0,0};
            float4 q0 = {0,0,0,0}, q1 = {0,0,0,0};
            int r = ga + lr;
            for (; r + 24 < gb; r += 32) {
                float4 v0 = __ldcs(&x4[r * NC4 + lc]);
                float4 v1 = __ldcs(&x4[(r + 8)  * NC4 + lc]);
                float4 v2 = __ldcs(&x4[(r + 16) * NC4 + lc]);
                float4 v3 = __ldcs(&x4[(r + 24) * NC4 + lc]);
                int i0 = r - r0;
                if (i0 < SROWS)      tile[i0 * NPAD + lc]        = v0;
                if (i0 + 8  < SROWS) tile[(i0 + 8)  * NPAD + lc] = v1;
                if (i0 + 16 < SROWS) tile[(i0 + 16) * NPAD + lc] = v2;
                if (i0 + 24 < SROWS) tile[(i0 + 24) * NPAD + lc] = v3;
                acc4(a0, q0, v0, sc); acc4(a1, q1, v1, sc);
                acc4(a0, q0, v2, sc); acc4(a1, q1, v3, sc);
            }
            for (; r < gb; r += 8) {
                float4 v0 = __ldcs(&x4[r * NC4 + lc]);
                int i0 = r - r0;
                if (i0 < SROWS) tile[i0 * NPAD + lc] = v0;
                acc4(a0, q0, v0, sc);
            }
            a0.x += a1.x; a0.y += a1.y; a0.z += a1.z; a0.w += a1.w;
            q0.x += q1.x; q0.y += q1.y; q0.z += q1.z; q0.w += q1.w;

            atomicAdd(&s_sum[lc*4+0], a0.x);
            atomicAdd(&s_sum[lc*4+1], a0.y);
            atomicAdd(&s_sum[lc*4+2], a0.z);
            atomicAdd(&s_sum[lc*4+3], a0.w);
            if (sc) {
                atomicAdd(&s_sq[lc*4+0], q0.x);
                atomicAdd(&s_sq[lc*4+1], q0.y);
                atomicAdd(&s_sq[lc*4+2], q0.z);
                atomicAdd(&s_sq[lc*4+3], q0.w);
            }
            __syncthreads();
            if (t < NTOT)  atomicAdd(&g_sum[g][t],   s_sum[t]);
            if (t < NSCAL) atomicAdd(&g_sumsq[g][t], s_sq[t]);
        }

        // ---------- grid barrier ----------
        __syncthreads();
        if (t == 0) {
            __threadfence();
            atomicAdd(&g_bar, 1u);
            unsigned target = (unsigned)GRID * (unsigned)(ph + 1);
            while (atomicAdd(&g_bar, 0u) < target) __nanosleep(128);
        }
        __syncthreads();

        // ---------- normalize from tile ----------
        for (int g = G0; g < G0 + GG; ++g) {
            int ga = max(r0, g_start[g]);
            int gb = min(r1, g_start[g + 1]);
            if (ga >= gb) continue;                   // uniform per CTA

            float deg   = (float)(g_start[g + 1] - g_start[g]);
            float inv_d = 1.0f / (deg + 1e-12f);

            const float4* gs4 = (const float4*)g_sum[g];
            float4 s4 = __ldcg(&gs4[lc]);
            float4 m4;
            m4.x = s4.x * inv_d; m4.y = s4.y * inv_d;
            m4.z = s4.z * inv_d; m4.w = s4.w * inv_d;

            if (t < 32) {   // lc==t, lr==0 -> m4 holds these scalar means
                const float4* gq4 = (const float4*)g_sumsq[g];
                float4 q = __ldcg(&gq4[t]);
                float v = (q.x * inv_d - m4.x * m4.x)
                        + (q.y * inv_d - m4.y * m4.y)
                        + (q.z * inv_d - m4.z * m4.z)
                        + (q.w * inv_d - m4.w * m4.w);
                #pragma unroll
                for (int off = 16; off > 0; off >>= 1)
                    v += __shfl_xor_sync(0xffffffffu, v, off);
                if (t == 0) *s_nrm = v * (1.0f / NSCAL);
            }
            __syncthreads();
            float inv = 1.0f / (sqrtf(*s_nrm) + EPSV);

            float4 A, B;
            {
                float* mp = (float*)&m4;
                float* ap = (float*)&A;
                float* bp = (float*)&B;
                #pragma unroll
                for (int k = 0; k < 4; ++k) {
                    if (sc) { ap[k] = w4[k] * inv; bp[k] = bi4[k] - mp[k] * ap[k]; }
                    else    { ap[k] = w4[k];       bp[k] = -mp[k] * w4[k]; }
                }
            }

            int r = ga + lr;
            for (; r + 8 < gb; r += 16) {
                int i0 = r - r0, i1 = r + 8 - r0;
                float4 v0 = (i0 < SROWS) ? tile[i0 * NPAD + lc]
                                         : __ldcg(&x4[r * NC4 + lc]);
                float4 v1 = (i1 < SROWS) ? tile[i1 * NPAD + lc]
                                         : __ldcg(&x4[(r + 8) * NC4 + lc]);
                __stcs(&o4[r * NC4 + lc],       fma4(v0, A, B));
                __stcs(&o4[(r + 8) * NC4 + lc], fma4(v1, A, B));
            }
            for (; r < gb; r += 8) {
                int i0 = r - r0;
                float4 v0 = (i0 < SROWS) ? tile[i0 * NPAD + lc]
                                         : __ldcg(&x4[r * NC4 + lc]);
                __stcs(&o4[r * NC4 + lc], fma4(v0, A, B));
            }
            __syncthreads();   // protect s_nrm before next graph
        }
    }
}

extern "C" void kernel_launch(void* const* d_in, const int* in_sizes, int n_in,
                              void* d_out, int out_size) {
    const float4* x4    = (const float4*)d_in[0];
    const float* weight = (const float*)d_in[1];
    const float* bias   = (const float*)d_in[2];
    const void*  batch  = d_in[3];
    int N = in_sizes[0] / NTOT;

    static int smem_set = 0;
    if (!smem_set) {
        cudaFuncSetAttribute(persist_kernel,
                             cudaFuncAttributeMaxDynamicSharedMemorySize,
                             SMEM_BYTES);
        smem_set = 1;
    }

    prep_kernel<<<(NB * NTOT + 255) / 256, 256>>>();
    bounds_kernel<<<1, 128>>>(batch, N);
    persist_kernel<<<GRID, THREADS, SMEM_BYTES>>>(
        x4, weight, bias, (float4*)d_out);
}